// round 11
// baseline (speedup 1.0000x reference)
#include <cuda_runtime.h>
#include <stdint.h>
#include <math.h>
#include <string.h>

// ---------------------------------------------------------------------------
// Constants: L_MAX=3, N_MAX_L=[8,6,4,2], C=32, K_L=[256,192,128,64]
// feature layout per atom (1920 floats): [l0:1x256][l1:3x192][l2:5x128][l3:7x64]
// element (l,m,k) at FOFF[l] + m*KL[l] + k
// ---------------------------------------------------------------------------
#define NT        34
#define NCG       3436
#define TPC_LEN   2226
#define NATOM_MAX 5000
#define NPAIR_MAX 100000
#define FSTRIDE   1920

#define LIST_L1 {0,0,0,0,1,1,1,1,1,1,1,1,1,2,2,2,2,2,2,2,2,2,2,2,3,3,3,3,3,3,3,3,3,3}
#define LIST_L2 {0,1,2,3,0,1,1,1,2,2,2,3,3,0,1,1,1,2,2,2,2,3,3,3,0,1,1,2,2,2,3,3,3,3}
#define LIST_LL {0,1,2,3,1,0,1,2,1,2,3,2,3,2,1,2,3,0,1,2,3,1,2,3,3,2,3,1,2,3,0,1,2,3}
#define LIST_CG {0,1,10,35,84,93,102,129,174,219,294,399,504,651,676,721,796,901,926,1001,1126,1301,1406,1581,1826,1875,1980,2127,2232,2407,2652,2701,2848,3093}

static const int HT_L1[NT] = LIST_L1;
static const int HT_L2[NT] = LIST_L2;
static const int HT_LL[NT] = LIST_LL;
static const int HT_CG[NT] = LIST_CG;

__host__ __device__ constexpr int KLf(int l)   { return 256 - 64 * l; }
__host__ __device__ constexpr int FOFFf(int l) { return l == 0 ? 0 : l == 1 ? 256 : l == 2 ? 832 : 1472; }

static const int H_RBOFF[4] = {0, 8, 14, 18};
static const int H_NMAX[4]  = {8, 6, 4, 2};

typedef unsigned long long ull;

// packed fp32x2 math (sm_10x; FFMA2 only reachable via PTX)
__device__ __forceinline__ ull f2_fma(ull a, ull b, ull c) {
    ull d; asm("fma.rn.f32x2 %0, %1, %2, %3;" : "=l"(d) : "l"(a), "l"(b), "l"(c)); return d;
}
__device__ __forceinline__ ull f2_mul(ull a, ull b) {
    ull d; asm("mul.rn.f32x2 %0, %1, %2;" : "=l"(d) : "l"(a), "l"(b)); return d;
}
__device__ __forceinline__ ull f2_dup(float x) {
    ull d; unsigned xi = __float_as_uint(x);
    asm("mov.b64 %0, {%1, %1};" : "=l"(d) : "r"(xi)); return d;
}
__device__ __forceinline__ void prefetch_l1(const void* p) {
    asm volatile("prefetch.global.L1 [%0];" :: "l"(p));
}

// ---------------------------------------------------------------------------
// Host-built tables (one H2D memcpy node per call)
// - cg: raw CG values (for wcomp)
// - tpc2: symmetrized TP coefficients, DUPLICATED {c,c} pairs, canonical order
// - ent/jse: wcomp entry table (merged-W build)
// ---------------------------------------------------------------------------
struct Blob {
    float cg[NCG];
    float tpc2[2 * TPC_LEN];
    unsigned short ent[NCG];
    int jse[256];
    int inv_off[60], inv_sh[60], inv_rb[60];
};

__device__ Blob  g_blob;
__device__ float g_bufA[(size_t)NATOM_MAX * FSTRIDE];
__device__ float g_bufB[(size_t)NATOM_MAX * FSTRIDE];
__device__ float g_wall[(size_t)NPAIR_MAX * 256];
__device__ float g_cemb[NATOM_MAX * 32];
__device__ int   g_counts[NATOM_MAX];
__device__ int   g_cursor[NATOM_MAX];
__device__ int   g_offsets[NATOM_MAX + 1];
__device__ int   g_sorted[NPAIR_MAX];

// ---------------------------------------------------------------------------
__global__ void cemb_kernel(const float* __restrict__ tab, const int* __restrict__ sp, int natoms) {
    int i = blockIdx.x * blockDim.x + threadIdx.x;
    if (i < natoms * 32) g_cemb[i] = tab[sp[i >> 5] * 32 + (i & 31)];
}

// ---------------------------------------------------------------------------
// counting sort of pairs by center
// ---------------------------------------------------------------------------
__global__ void zero_kernel(int natoms) {
    int i = blockIdx.x * blockDim.x + threadIdx.x;
    if (i < natoms) { g_counts[i] = 0; g_cursor[i] = 0; }
}
__global__ void hist_kernel(const int* __restrict__ centers, int np) {
    int p = blockIdx.x * blockDim.x + threadIdx.x;
    if (p < np) atomicAdd(&g_counts[centers[p]], 1);
}
__global__ void scan_kernel(int natoms) {
    __shared__ int ssum[1024];
    int t = threadIdx.x;
    int loc[5]; int s = 0;
#pragma unroll
    for (int i = 0; i < 5; i++) {
        int idx = t * 5 + i;
        loc[i] = s;
        int v = (idx < natoms) ? g_counts[idx] : 0;
        s += v;
    }
    ssum[t] = s;
    __syncthreads();
    for (int off = 1; off < 1024; off <<= 1) {
        int v = (t >= off) ? ssum[t - off] : 0;
        __syncthreads();
        ssum[t] += v;
        __syncthreads();
    }
    int pre = (t > 0) ? ssum[t - 1] : 0;
#pragma unroll
    for (int i = 0; i < 5; i++) {
        int idx = t * 5 + i;
        if (idx <= natoms) g_offsets[idx] = pre + loc[i];
    }
}
__global__ void rank_kernel(const int* __restrict__ centers, int np) {
    int p = blockIdx.x * blockDim.x + threadIdx.x;
    if (p < np) {
        int c = centers[p];
        int r = atomicAdd(&g_cursor[c], 1);
        g_sorted[g_offsets[c] + r] = p;
    }
}

// ---------------------------------------------------------------------------
// merged edge-weight build: g_wall[p][j], j = (l2^2+b)*16 + L^2+M, 256 outputs.
// ---------------------------------------------------------------------------
#define PPB 16
__global__ void __launch_bounds__(128) wcomp_kernel(
    const float* __restrict__ sh, const float* __restrict__ rb, int np) {
    __shared__ float s_cg[NCG];
    __shared__ unsigned short s_ent[NCG];
    __shared__ int s_jse[256];
    __shared__ float s_edge[4][16];
    int tid = threadIdx.x;
    for (int i = tid; i < NCG; i += 128) { s_cg[i] = g_blob.cg[i]; s_ent[i] = g_blob.ent[i]; }
    for (int i = tid; i < 256; i += 128) s_jse[i] = g_blob.jse[i];
    __syncthreads();
    int warp = tid >> 5, lane = tid & 31;
#pragma unroll
    for (int pi = 0; pi < PPB / 4; pi++) {
        int p = blockIdx.x * PPB + warp + pi * 4;
        if (p >= np) break;
        if (lane < 16) {
            int l = (lane >= 9) ? 3 : (lane >= 4) ? 2 : (lane >= 1) ? 1 : 0;
            int rboff = (l == 3) ? 18 : (l == 2) ? 14 : (l == 1) ? 8 : 0;
            int rbsz = 8 - 2 * l;
            float rs = 0.f;
            for (int n = 0; n < rbsz; n++) rs += rb[(size_t)p * 20 + rboff + n];
            s_edge[warp][lane] = 0.1f * sh[(size_t)p * 16 + lane] * rs;
        }
        __syncwarp();
        float* wp = g_wall + (size_t)p * 256;
#pragma unroll
        for (int ii = 0; ii < 8; ii++) {
            int j = lane + 32 * ii;
            int se = s_jse[j];
            int st = se >> 16, cnt = se & 0xffff;
            float s = 0.f;
            for (int e = 0; e < cnt; e++) {
                unsigned en = s_ent[st + e];
                s += s_edge[warp][en >> 12] * s_cg[en & 0xfff];
            }
            wp[j] = s;
        }
        __syncwarp();
    }
}

// ---------------------------------------------------------------------------
// invariant MP, gather form w/ double-buffered staging.
// ---------------------------------------------------------------------------
__global__ void __launch_bounds__(128) inv_kernel(
    const float* __restrict__ sh, const float* __restrict__ rb,
    const int* __restrict__ neighbors, float* __restrict__ bufA, int natoms) {
    __shared__ float s_in[2][68];   // [0:16) sh, [16:36) rb, [36:68) emb
    int c = blockIdx.x;
    int tid = threadIdx.x, warp = tid >> 5, lane = tid & 31;
    int offj[15], shi[15], rbi[15];
#pragma unroll
    for (int ii = 0; ii < 15; ii++) {
        int j = warp + 4 * ii;
        offj[ii] = g_blob.inv_off[j];
        shi[ii]  = g_blob.inv_sh[j];
        rbi[ii]  = g_blob.inv_rb[j];
    }
    float acc[15];
#pragma unroll
    for (int ii = 0; ii < 15; ii++) acc[ii] = 0.f;

    int beg = g_offsets[c], end = g_offsets[c + 1];
    if (beg < end) {
        int p0 = g_sorted[beg];
        if (tid < 16)      s_in[0][tid] = sh[(size_t)p0 * 16 + tid];
        else if (tid < 36) s_in[0][tid] = rb[(size_t)p0 * 20 + (tid - 16)];
        else if (tid < 68) s_in[0][tid] = g_cemb[neighbors[p0] * 32 + (tid - 36)];
    }
    __syncthreads();
    for (int i = beg; i < end; i++) {
        int cur = (i - beg) & 1;
        float nst = 0.f;
        bool more = (i + 1 < end);
        if (more && tid < 68) {
            int pn = g_sorted[i + 1];
            if (tid < 16)      nst = sh[(size_t)pn * 16 + tid];
            else if (tid < 36) nst = rb[(size_t)pn * 20 + (tid - 16)];
            else               nst = g_cemb[neighbors[pn] * 32 + (tid - 36)];
        }
        float e = s_in[cur][36 + lane];
#pragma unroll
        for (int ii = 0; ii < 15; ii++)
            acc[ii] += s_in[cur][shi[ii]] * s_in[cur][16 + rbi[ii]] * e;
        if (more && tid < 68) s_in[cur ^ 1][tid] = nst;
        __syncthreads();
    }
    float* fb = bufA + (size_t)c * FSTRIDE;
#pragma unroll
    for (int ii = 0; ii < 15; ii++) fb[offj[ii] + lane] = 0.01f * acc[ii];
}

// ---------------------------------------------------------------------------
// symmetrized in-place CG tensor product: feat += 0.1*TP(feat,feat).
// Unordered products A[p]*A[q] (p<=q), host-merged coefficients stored as
// duplicated {c,c} pairs -> 1 LDS.64 + 1 FFMA2 per term (2 issues/term).
// Heavy band: 1828 terms (vs 3436 unsymmetrized).
// ---------------------------------------------------------------------------
template <int LV>
__device__ __forceinline__ void tp_body(float* __restrict__ fb, int k, const float* s_tpc2) {
    constexpr int MM = (LV + 1) * (LV + 1);
    ull A[MM], acc[MM];
#pragma unroll
    for (int l = 0; l <= LV; l++)
#pragma unroll
        for (int m = 0; m < 2 * l + 1; m++)
            A[l * l + m] = *reinterpret_cast<const ull*>(&fb[FOFFf(l) + m * KLf(l) + k]);
#pragma unroll
    for (int i = 0; i < MM; i++) acc[i] = 0ull;

    int idx = 0;
#pragma unroll
    for (int l1 = 0; l1 < 4; l1++)
#pragma unroll
    for (int a = 0; a < 2 * l1 + 1; a++)
#pragma unroll
    for (int l2 = l1; l2 < 4; l2++)
#pragma unroll
    for (int b = (l2 == l1 ? a : 0); b < 2 * l2 + 1; b++) {
        const bool act0 = (l1 <= LV) && (l2 <= LV);
        const int ia = (l1 <= LV) ? l1 * l1 + a : 0;
        const int ib = (l2 <= LV) ? l2 * l2 + b : 0;
        ull P = 0;
        if (act0) P = f2_mul(A[ia], A[ib]);
#pragma unroll
        for (int L = l2 - l1; L <= ((l1 + l2 < 3) ? (l1 + l2) : 3); L++) {
            if (act0 && L <= LV) {
#pragma unroll
                for (int M = 0; M < 2 * L + 1; M++) {
                    ull c2 = *reinterpret_cast<const ull*>(&s_tpc2[2 * (idx + M)]);
                    acc[L * L + M] = f2_fma(c2, P, acc[L * L + M]);
                }
            }
            idx += 2 * L + 2;   // padded group stride (canonical)
        }
    }
    ull sc = f2_dup(0.1f);
#pragma unroll
    for (int l = 0; l <= LV; l++)
#pragma unroll
        for (int m = 0; m < 2 * l + 1; m++) {
            int i = l * l + m;
            *reinterpret_cast<ull*>(&fb[FOFFf(l) + m * KLf(l) + k]) = f2_fma(sc, acc[i], A[i]);
        }
}

__global__ void __launch_bounds__(512) tp_fused_kernel(float* __restrict__ buf, int natoms) {
    __shared__ __align__(16) float s_tpc2[2 * TPC_LEN];
    for (int i = threadIdx.x; i < 2 * TPC_LEN; i += 512) s_tpc2[i] = g_blob.tpc2[i];
    __syncthreads();
    int warp = threadIdx.x >> 5, lane = threadIdx.x & 31;
    int atomI = blockIdx.x * 4 + (warp >> 2);
    if (atomI >= natoms) return;
    int bk = ((warp & 3) + atomI) & 3;   // band; LV = 3 - bk
    int k = bk * 64 + lane * 2;
    float* fb = buf + (size_t)atomI * FSTRIDE;
    if (bk == 0)      tp_body<3>(fb, k, s_tpc2);
    else if (bk == 1) tp_body<2>(fb, k, s_tpc2);
    else if (bk == 2) tp_body<1>(fb, k, s_tpc2);
    else              tp_body<0>(fb, k, s_tpc2);
}

// ---------------------------------------------------------------------------
// equivariant MP, gather form, merged dense W (16x16 per pair), duplicated-W
// smem (LDS.64+FFMA2 per term), embed fold, double-buffered staging, and L1
// prefetch of the next pair's neighbor feature block.
// ---------------------------------------------------------------------------
template <int LV>
__device__ __forceinline__ void eq_acc2(const float* __restrict__ fan, ull ce2,
                                        const float* __restrict__ sw2, int k, ull* acc) {
    ull f[(LV + 1) * (LV + 1)];
#pragma unroll
    for (int l = 0; l <= LV; l++)
#pragma unroll
        for (int b = 0; b < 2 * l + 1; b++) {
            ull v = *reinterpret_cast<const ull*>(&fan[FOFFf(l) + b * KLf(l) + k]);
            f[l * l + b] = f2_mul(v, ce2);   // fold embed_centers
        }
#pragma unroll
    for (int l2 = 0; l2 <= LV; l2++)
#pragma unroll
        for (int b = 0; b < 2 * l2 + 1; b++) {
            ull fb = f[l2 * l2 + b];
            const int lm2 = l2 * l2 + b;
#pragma unroll
            for (int L = 0; L <= LV; L++)
#pragma unroll
                for (int M = 0; M < 2 * L + 1; M++) {
                    ull w2 = *reinterpret_cast<const ull*>(&sw2[2 * (lm2 * 16 + L * L + M)]);
                    acc[L * L + M] = f2_fma(w2, fb, acc[L * L + M]);
                }
        }
}

template <int LV>
__device__ __forceinline__ void eq_write2(float* __restrict__ mpb, int k, const ull* acc) {
    ull sc = f2_dup(0.1f);
#pragma unroll
    for (int L = 0; L <= LV; L++)
#pragma unroll
        for (int M = 0; M < 2 * L + 1; M++) {
            ull v = f2_mul(sc, acc[L * L + M]);
            *reinterpret_cast<ull*>(&mpb[FOFFf(L) + M * KLf(L) + k]) = v;
        }
}

__global__ void __launch_bounds__(128) eq_kernel(
    const int* __restrict__ neighbors,
    const float* __restrict__ bufA, float* __restrict__ bufB, int natoms) {
    __shared__ __align__(16) float s_w2[2][512];
    int c = blockIdx.x;
    int tid = threadIdx.x, warp = tid >> 5, lane = tid & 31;
    int bk = (warp + c) & 3;          // band; LV = 3 - bk
    int k = bk * 64 + lane * 2;
    ull acc[16];
#pragma unroll
    for (int i = 0; i < 16; i++) acc[i] = 0ull;

    int beg = g_offsets[c], end = g_offsets[c + 1];
    int nbr_cur = 0;
    if (beg < end) {
        int p0 = g_sorted[beg];
        nbr_cur = neighbors[p0];
        const float* wp = g_wall + (size_t)p0 * 256;
#pragma unroll
        for (int jj = 0; jj < 2; jj++) {
            int j = tid + jj * 128;
            float v = wp[j];
            *reinterpret_cast<float2*>(&s_w2[0][2 * j]) = make_float2(v, v);
        }
    }
    __syncthreads();
    for (int i = beg; i < end; i++) {
        int cur = (i - beg) & 1;
        bool more = (i + 1 < end);
        float nst0 = 0.f, nst1 = 0.f;
        int nbr_next = 0;
        if (more) {
            int pn = g_sorted[i + 1];
            nbr_next = neighbors[pn];
            const float* wp = g_wall + (size_t)pn * 256;
            nst0 = wp[tid];
            nst1 = wp[tid + 128];
            // L1 prefetch of next neighbor's feature block (60 x 128B lines)
            const float* pf = bufA + (size_t)nbr_next * FSTRIDE;
            if (tid < 60) prefetch_l1(pf + tid * 32);
            else if (tid == 60) prefetch_l1(&g_cemb[nbr_next * 32]);
        }
        const float* fan = bufA + (size_t)nbr_cur * FSTRIDE;
        float2 cef = *reinterpret_cast<const float2*>(&g_cemb[nbr_cur * 32 + 2 * (lane & 15)]);
        ull ce2 = *reinterpret_cast<ull*>(&cef);
        const float* sw = s_w2[cur];
        if (bk == 0)      eq_acc2<3>(fan, ce2, sw, k, acc);
        else if (bk == 1) eq_acc2<2>(fan, ce2, sw, k, acc);
        else if (bk == 2) eq_acc2<1>(fan, ce2, sw, k, acc);
        else              eq_acc2<0>(fan, ce2, sw, k, acc);
        if (more) {
            *reinterpret_cast<float2*>(&s_w2[cur ^ 1][2 * tid]) = make_float2(nst0, nst0);
            *reinterpret_cast<float2*>(&s_w2[cur ^ 1][2 * (tid + 128)]) = make_float2(nst1, nst1);
            nbr_cur = nbr_next;
        }
        __syncthreads();
    }
    float* mpb = bufB + (size_t)c * FSTRIDE;
    if (bk == 0)      eq_write2<3>(mpb, k, acc);
    else if (bk == 1) eq_write2<2>(mpb, k, acc);
    else if (bk == 2) eq_write2<1>(mpb, k, acc);
    else              eq_write2<0>(mpb, k, acc);
}

// ---------------------------------------------------------------------------
// energy: out[n] = sum_k buf[n,0,k] * cemb[n,k%32] * w[k] + b   (embed folded)
// ---------------------------------------------------------------------------
__global__ void energy_kernel(const float* __restrict__ buf,
                              const float* __restrict__ we, const float* __restrict__ be,
                              float* __restrict__ out, int natoms) {
    int atomI = blockIdx.x * 4 + (threadIdx.x >> 5);
    int lane = threadIdx.x & 31;
    if (atomI >= natoms) return;
    float e = g_cemb[atomI * 32 + lane];
    const float* fb = buf + (size_t)atomI * FSTRIDE;
    float s = 0.f;
#pragma unroll
    for (int kk = 0; kk < 8; kk++) s += fb[kk * 32 + lane] * we[kk * 32 + lane];
    s *= e;
#pragma unroll
    for (int o = 16; o > 0; o >>= 1) s += __shfl_xor_sync(0xffffffffu, s, o);
    if (lane == 0) out[atomI] = s + be[0];
}

// ---------------------------------------------------------------------------
// host: bit-exact numpy legacy RandomState(0).randn + table construction
// ---------------------------------------------------------------------------
static uint32_t s_mt[624];
static int s_mti;
static uint32_t mt_next() {
    if (s_mti >= 624) {
        for (int kk = 0; kk < 624; kk++) {
            uint32_t y = (s_mt[kk] & 0x80000000u) | (s_mt[(kk + 1) % 624] & 0x7fffffffu);
            s_mt[kk] = s_mt[(kk + 397) % 624] ^ (y >> 1) ^ ((y & 1u) ? 2567483615u : 0u);
        }
        s_mti = 0;
    }
    uint32_t y = s_mt[s_mti++];
    y ^= y >> 11;
    y ^= (y << 7) & 2636928640u;
    y ^= (y << 15) & 4022730752u;
    y ^= y >> 18;
    return y;
}
static double mt_double() {
    uint32_t a = mt_next() >> 5, b = mt_next() >> 6;
    return (a * 67108864.0 + b) / 9007199254740992.0;
}

static void build_blob(Blob& B) {
    uint32_t seed = 0;
    for (int pos = 0; pos < 624; pos++) {
        s_mt[pos] = seed;
        seed = 1812433253u * (seed ^ (seed >> 30)) + (uint32_t)pos + 1u;
    }
    s_mti = 624;
    int has_g = 0;
    double gcache = 0.0;
    for (int t = 0; t < NCG; t++) {
        double g;
        if (has_g) { g = gcache; has_g = 0; }
        else {
            double x1, x2, r2, f;
            do {
                x1 = 2.0 * mt_double() - 1.0;
                x2 = 2.0 * mt_double() - 1.0;
                r2 = x1 * x1 + x2 * x2;
            } while (r2 >= 1.0 || r2 == 0.0);
            f = sqrt(-2.0 * log(r2) / r2);
            gcache = f * x1;
            has_g = 1;
            g = f * x2;
        }
        B.cg[t] = (float)(g * 0.2);
    }
    // triple lookup
    int tmap[4][4][4];
    for (int i = 0; i < 64; i++) (&tmap[0][0][0])[i] = -1;
    for (int tt = 0; tt < NT; tt++) tmap[HT_L1[tt]][HT_L2[tt]][HT_LL[tt]] = tt;
    auto cgv = [&](int l1, int l2, int L, int a, int b, int M) -> float {
        int tt = tmap[l1][l2][L];
        return B.cg[HT_CG[tt] + (a * (2 * l2 + 1) + b) * (2 * L + 1) + M];
    };
    // symmetrized TP table, canonical order, duplicated {c,c} storage
    {
        int idx = 0;
        for (int l1 = 0; l1 < 4; l1++)
        for (int a = 0; a < 2 * l1 + 1; a++)
        for (int l2 = l1; l2 < 4; l2++)
        for (int b = (l2 == l1 ? a : 0); b < 2 * l2 + 1; b++)
        for (int L = l2 - l1; L <= ((l1 + l2 < 3) ? (l1 + l2) : 3); L++) {
            for (int M = 0; M < 2 * L + 1; M++) {
                float c = cgv(l1, l2, L, a, b, M);
                if (!(l1 == l2 && a == b)) c += cgv(l2, l1, L, b, a, M);
                B.tpc2[2 * (idx + M)]     = c;
                B.tpc2[2 * (idx + M) + 1] = c;
            }
            B.tpc2[2 * (idx + 2 * L + 1)]     = 0.f;   // pad slot
            B.tpc2[2 * (idx + 2 * L + 1) + 1] = 0.f;
            idx += 2 * L + 2;
        }
        // idx == TPC_LEN by construction
    }
    // merged-W entry table: per output j=(l2^2+b)*16 + L^2+M
    static unsigned short tmp[256][16];
    static int cnt[256];
    memset(cnt, 0, sizeof(cnt));
    for (int tt = 0; tt < NT; tt++) {
        int l1 = HT_L1[tt], l2 = HT_L2[tt], L = HT_LL[tt];
        for (int a = 0; a < 2 * l1 + 1; a++)
            for (int b = 0; b < 2 * l2 + 1; b++)
                for (int M = 0; M < 2 * L + 1; M++) {
                    int j = (l2 * l2 + b) * 16 + L * L + M;
                    int cg_off = HT_CG[tt] + (a * (2 * l2 + 1) + b) * (2 * L + 1) + M;
                    tmp[j][cnt[j]++] = (unsigned short)(((l1 * l1 + a) << 12) | cg_off);
                }
    }
    int pos = 0;
    for (int j = 0; j < 256; j++) {
        B.jse[j] = (pos << 16) | cnt[j];
        for (int e = 0; e < cnt[j]; e++) B.ent[pos++] = tmp[j][e];
    }
    // invariant combo table
    int j2 = 0;
    for (int l = 0; l < 4; l++)
        for (int m = 0; m < 2 * l + 1; m++)
            for (int n = 0; n < H_NMAX[l]; n++) {
                B.inv_off[j2] = FOFFf(l) + m * KLf(l) + n * 32;
                B.inv_sh[j2]  = l * l + m;
                B.inv_rb[j2]  = H_RBOFF[l] + n;
                j2++;
            }
}

static Blob h_blob;   // static: must outlive graph replays (memcpy node source)

// ---------------------------------------------------------------------------
extern "C" void kernel_launch(void* const* d_in, const int* in_sizes, int n_in,
                              void* d_out, int out_size) {
    const float* sh        = (const float*)d_in[0];
    const float* rb        = (const float*)d_in[1];
    const float* emb_table = (const float*)d_in[2];
    const float* w_energy  = (const float*)d_in[3];
    const float* b_energy  = (const float*)d_in[4];
    const int*   species   = (const int*)d_in[5];
    const int*   centers   = (const int*)d_in[6];
    const int*   neighbors = (const int*)d_in[7];
    int natoms = in_sizes[5];
    int np     = in_sizes[6];
    if (natoms > NATOM_MAX) natoms = NATOM_MAX;
    if (np > NPAIR_MAX)     np = NPAIR_MAX;
    float* out = (float*)d_out;

    build_blob(h_blob);
    cudaMemcpyToSymbolAsync(g_blob, &h_blob, sizeof(Blob), 0, cudaMemcpyHostToDevice, 0);

    float *bufA = nullptr, *bufB = nullptr;
    cudaGetSymbolAddress((void**)&bufA, g_bufA);
    cudaGetSymbolAddress((void**)&bufB, g_bufB);

    // embeddings + counting sort of pairs by center
    cemb_kernel<<<(natoms * 32 + 255) / 256, 256>>>(emb_table, species, natoms);
    zero_kernel<<<(natoms + 255) / 256, 256>>>(natoms);
    hist_kernel<<<(np + 255) / 256, 256>>>(centers, np);
    scan_kernel<<<1, 1024>>>(natoms);
    rank_kernel<<<(np + 255) / 256, 256>>>(centers, np);

    // merged per-pair edge-weight matrices (dense 16x16)
    wcomp_kernel<<<(np + PPB - 1) / PPB, 128>>>(sh, rb, np);

    // invariant MP (gather) -> bufA
    inv_kernel<<<natoms, 128>>>(sh, rb, neighbors, bufA, natoms);

    // cg_iterate #1 (symmetrized TP, duplicated coefficients)
    tp_fused_kernel<<<(natoms + 3) / 4, 512>>>(bufA, natoms);

    // equivariant MP: reads bufA (embed folded) + g_wall, writes bufB
    eq_kernel<<<natoms, 128>>>(neighbors, bufA, bufB, natoms);

    // cg_iterate #2
    tp_fused_kernel<<<(natoms + 3) / 4, 512>>>(bufB, natoms);

    // final embed folded into energy readout
    energy_kernel<<<(natoms + 3) / 4, 128>>>(bufB, w_energy, b_energy, out, natoms);
}

// round 14
// speedup vs baseline: 1.5428x; 1.5428x over previous
#include <cuda_runtime.h>
#include <stdint.h>
#include <math.h>
#include <string.h>

// ---------------------------------------------------------------------------
// Constants: L_MAX=3, N_MAX_L=[8,6,4,2], C=32, K_L=[256,192,128,64]
// feature layout per atom (1920 floats): [l0:1x256][l1:3x192][l2:5x128][l3:7x64]
// element (l,m,k) at FOFF[l] + m*KL[l] + k
// ---------------------------------------------------------------------------
#define NT        34
#define NCG       3436
#define NATOM_MAX 5000
#define NPAIR_MAX 100000
#define FSTRIDE   1920

constexpr int CT_L1[NT] = {0,0,0,0,1,1,1,1,1,1,1,1,1,2,2,2,2,2,2,2,2,2,2,2,3,3,3,3,3,3,3,3,3,3};
constexpr int CT_L2[NT] = {0,1,2,3,0,1,1,1,2,2,2,3,3,0,1,1,1,2,2,2,2,3,3,3,0,1,1,2,2,2,3,3,3,3};
constexpr int CT_LL[NT] = {0,1,2,3,1,0,1,2,1,2,3,2,3,2,1,2,3,0,1,2,3,1,2,3,3,2,3,1,2,3,0,1,2,3};
constexpr int CT_CG[NT] = {0,1,10,35,84,93,102,129,174,219,294,399,504,651,676,721,796,901,926,1001,1126,1301,1406,1581,1826,1875,1980,2127,2232,2407,2652,2701,2848,3093};

__host__ __device__ constexpr int KLf(int l)   { return 256 - 64 * l; }
__host__ __device__ constexpr int FOFFf(int l) { return l == 0 ? 0 : l == 1 ? 256 : l == 2 ? 832 : 1472; }

static const int H_RBOFF[4] = {0, 8, 14, 18};
static const int H_NMAX[4]  = {8, 6, 4, 2};

typedef unsigned long long ull;

// packed fp32x2 math (sm_10x; FFMA2 only reachable via PTX) — used by eq only
__device__ __forceinline__ ull f2_fma(ull a, ull b, ull c) {
    ull d; asm("fma.rn.f32x2 %0, %1, %2, %3;" : "=l"(d) : "l"(a), "l"(b), "l"(c)); return d;
}
__device__ __forceinline__ ull f2_mul(ull a, ull b) {
    ull d; asm("mul.rn.f32x2 %0, %1, %2;" : "=l"(d) : "l"(a), "l"(b)); return d;
}
__device__ __forceinline__ ull f2_dup(float x) {
    ull d; unsigned xi = __float_as_uint(x);
    asm("mov.b64 %0, {%1, %1};" : "=l"(d) : "r"(xi)); return d;
}

// ===========================================================================
// COMPILE-TIME numpy legacy RandomState(0).randn stream (MT19937 + polar
// gauss w/ cache). Chunked into 16 separate constexpr evaluations to stay
// under per-variable constexpr step limits.
// ===========================================================================
struct RS {
    unsigned mt[624];
    int mti;
    int has_g;
    double gc;
};
constexpr RS rs_init() {
    RS s{};
    unsigned seed = 0;
    for (int pos = 0; pos < 624; pos++) {
        s.mt[pos] = seed;
        seed = 1812433253u * (seed ^ (seed >> 30)) + (unsigned)pos + 1u;
    }
    s.mti = 624;
    s.has_g = 0;
    s.gc = 0.0;
    return s;
}
constexpr unsigned rs_next(RS& s) {
    if (s.mti >= 624) {
        for (int k = 0; k < 624; k++) {
            unsigned y = (s.mt[k] & 0x80000000u) | (s.mt[(k + 1) % 624] & 0x7fffffffu);
            s.mt[k] = s.mt[(k + 397) % 624] ^ (y >> 1) ^ ((y & 1u) ? 2567483615u : 0u);
        }
        s.mti = 0;
    }
    unsigned y = s.mt[s.mti++];
    y ^= y >> 11;
    y ^= (y << 7) & 2636928640u;
    y ^= (y << 15) & 4022730752u;
    y ^= y >> 18;
    return y;
}
constexpr double rs_double(RS& s) {
    unsigned a = rs_next(s) >> 5, b = rs_next(s) >> 6;
    return (a * 67108864.0 + b) / 9007199254740992.0;
}
constexpr double c_log(double x) {   // x in (0,1); ~1e-26 series tail
    int k = 0;
    double m = x;
    while (m < 0.5) { m *= 2.0; k++; }
    double t = (m - 1.0) / (m + 1.0);
    double t2 = t * t, term = t, sum = 0.0;
    for (int i = 0; i < 27; i++) { sum += term / (double)(2 * i + 1); term *= t2; }
    return 2.0 * sum - (double)k * 0.6931471805599453094172321214582;
}
constexpr double c_sqrt(double x) {
    double y = x, s = 1.0;
    while (y > 4.0)  { y *= 0.25; s *= 2.0; }
    while (y < 0.25) { y *= 4.0;  s *= 0.5; }
    double r = 1.0;
    for (int i = 0; i < 40; i++) r = 0.5 * (r + y / r);
    return r * s;
}
constexpr double rs_gauss(RS& s) {
    if (s.has_g) { s.has_g = 0; return s.gc; }
    double x1 = 0.0, x2 = 0.0, r2 = 0.0;
    do {
        x1 = 2.0 * rs_double(s) - 1.0;
        x2 = 2.0 * rs_double(s) - 1.0;
        r2 = x1 * x1 + x2 * x2;
    } while (r2 >= 1.0 || r2 == 0.0);
    double f = c_sqrt(-2.0 * c_log(r2) / r2);
    s.gc = f * x1;
    s.has_g = 1;
    return f * x2;
}

#define CGCHUNK 215
struct CGChunk { float v[CGCHUNK]; RS st; };
constexpr CGChunk cg_chunk(RS st) {
    CGChunk c{};
    for (int i = 0; i < CGCHUNK; i++) c.v[i] = (float)(rs_gauss(st) * 0.2);
    c.st = st;
    return c;
}
constexpr CGChunk CGC0  = cg_chunk(rs_init());
constexpr CGChunk CGC1  = cg_chunk(CGC0.st);
constexpr CGChunk CGC2  = cg_chunk(CGC1.st);
constexpr CGChunk CGC3  = cg_chunk(CGC2.st);
constexpr CGChunk CGC4  = cg_chunk(CGC3.st);
constexpr CGChunk CGC5  = cg_chunk(CGC4.st);
constexpr CGChunk CGC6  = cg_chunk(CGC5.st);
constexpr CGChunk CGC7  = cg_chunk(CGC6.st);
constexpr CGChunk CGC8  = cg_chunk(CGC7.st);
constexpr CGChunk CGC9  = cg_chunk(CGC8.st);
constexpr CGChunk CGC10 = cg_chunk(CGC9.st);
constexpr CGChunk CGC11 = cg_chunk(CGC10.st);
constexpr CGChunk CGC12 = cg_chunk(CGC11.st);
constexpr CGChunk CGC13 = cg_chunk(CGC12.st);
constexpr CGChunk CGC14 = cg_chunk(CGC13.st);
constexpr CGChunk CGC15 = cg_chunk(CGC14.st);

constexpr float cg_ct(int i) {
    return i < 215*1  ? CGC0.v[i]
         : i < 215*2  ? CGC1.v[i - 215*1]
         : i < 215*3  ? CGC2.v[i - 215*2]
         : i < 215*4  ? CGC3.v[i - 215*3]
         : i < 215*5  ? CGC4.v[i - 215*4]
         : i < 215*6  ? CGC5.v[i - 215*5]
         : i < 215*7  ? CGC6.v[i - 215*6]
         : i < 215*8  ? CGC7.v[i - 215*7]
         : i < 215*9  ? CGC8.v[i - 215*8]
         : i < 215*10 ? CGC9.v[i - 215*9]
         : i < 215*11 ? CGC10.v[i - 215*10]
         : i < 215*12 ? CGC11.v[i - 215*11]
         : i < 215*13 ? CGC12.v[i - 215*12]
         : i < 215*14 ? CGC13.v[i - 215*13]
         : i < 215*15 ? CGC14.v[i - 215*14]
         :              CGC15.v[i - 215*15];
}

constexpr int tmap_ct(int l1, int l2, int L) {
    for (int tt = 0; tt < NT; tt++)
        if (CT_L1[tt] == l1 && CT_L2[tt] == l2 && CT_LL[tt] == L) return tt;
    return -1;
}
constexpr float cgv_ct(int l1, int l2, int L, int a, int b, int M) {
    int tt = tmap_ct(l1, l2, L);
    return cg_ct(CT_CG[tt] + (a * (2 * l2 + 1) + b) * (2 * L + 1) + M);
}

// symmetrized TP term list (unordered products, host-merged coefficients)
#define MAXT 1828
struct TermList { short p[MAXT]; short q[MAXT]; short o[MAXT]; float c[MAXT]; int n; };
constexpr TermList make_terms(int LV) {
    TermList T{};
    int n = 0;
    for (int l1 = 0; l1 <= LV; l1++)
    for (int a = 0; a < 2 * l1 + 1; a++)
    for (int l2 = l1; l2 <= LV; l2++)
    for (int b = (l2 == l1 ? a : 0); b < 2 * l2 + 1; b++)
    for (int L = l2 - l1; L <= ((l1 + l2 < 3) ? (l1 + l2) : 3); L++) {
        if (L > LV) continue;
        for (int M = 0; M < 2 * L + 1; M++) {
            float c = cgv_ct(l1, l2, L, a, b, M);
            if (!(l1 == l2 && a == b)) c += cgv_ct(l2, l1, L, b, a, M);
            T.p[n] = (short)(l1 * l1 + a);
            T.q[n] = (short)(l2 * l2 + b);
            T.o[n] = (short)(L * L + M);
            T.c[n] = c;
            n++;
        }
    }
    T.n = n;
    return T;
}
template <int LV> struct TL_t { static constexpr TermList v = make_terms(LV); };
static_assert(TL_t<3>::v.n <= MAXT, "term overflow");

// binary-recursive term runner: every coefficient is an FFMA immediate
template <int LV, int I, int N, int MM>
__device__ __forceinline__ void tp_run(const float (&A0)[MM], const float (&A1)[MM],
                                       float (&c0)[MM], float (&c1)[MM],
                                       float& p0, float& p1) {
    if constexpr (N == 1) {
        constexpr int pp = TL_t<LV>::v.p[I];
        constexpr int qq = TL_t<LV>::v.q[I];
        constexpr int oo = TL_t<LV>::v.o[I];
        constexpr float cc = TL_t<LV>::v.c[I];
        constexpr bool fresh = (I == 0) || (TL_t<LV>::v.p[I - 1] != pp) ||
                               (TL_t<LV>::v.q[I - 1] != qq);
        if constexpr (fresh) { p0 = A0[pp] * A0[qq]; p1 = A1[pp] * A1[qq]; }
        c0[oo] = fmaf(cc, p0, c0[oo]);
        c1[oo] = fmaf(cc, p1, c1[oo]);
    } else if constexpr (N > 1) {
        constexpr int H = N / 2;
        tp_run<LV, I, H, MM>(A0, A1, c0, c1, p0, p1);
        tp_run<LV, I + H, N - H, MM>(A0, A1, c0, c1, p0, p1);
    }
}

// ---------------------------------------------------------------------------
// Host-built tables (one H2D memcpy node per call) — wcomp + inv only
// ---------------------------------------------------------------------------
struct Blob {
    float cg[NCG];
    unsigned short ent[NCG];
    int jse[256];
    int inv_off[60], inv_sh[60], inv_rb[60];
};

__device__ Blob  g_blob;
__device__ float g_bufA[(size_t)NATOM_MAX * FSTRIDE];
__device__ float g_bufB[(size_t)NATOM_MAX * FSTRIDE];
__device__ float g_wall[(size_t)NPAIR_MAX * 256];
__device__ float g_cemb[NATOM_MAX * 32];
__device__ int   g_counts[NATOM_MAX];
__device__ int   g_cursor[NATOM_MAX];
__device__ int   g_offsets[NATOM_MAX + 1];
__device__ int   g_sorted[NPAIR_MAX];

// ---------------------------------------------------------------------------
__global__ void cemb_kernel(const float* __restrict__ tab, const int* __restrict__ sp, int natoms) {
    int i = blockIdx.x * blockDim.x + threadIdx.x;
    if (i < natoms * 32) g_cemb[i] = tab[sp[i >> 5] * 32 + (i & 31)];
}

// counting sort of pairs by center -------------------------------------------
__global__ void zero_kernel(int natoms) {
    int i = blockIdx.x * blockDim.x + threadIdx.x;
    if (i < natoms) { g_counts[i] = 0; g_cursor[i] = 0; }
}
__global__ void hist_kernel(const int* __restrict__ centers, int np) {
    int p = blockIdx.x * blockDim.x + threadIdx.x;
    if (p < np) atomicAdd(&g_counts[centers[p]], 1);
}
__global__ void scan_kernel(int natoms) {
    __shared__ int ssum[1024];
    int t = threadIdx.x;
    int loc[5]; int s = 0;
#pragma unroll
    for (int i = 0; i < 5; i++) {
        int idx = t * 5 + i;
        loc[i] = s;
        int v = (idx < natoms) ? g_counts[idx] : 0;
        s += v;
    }
    ssum[t] = s;
    __syncthreads();
    for (int off = 1; off < 1024; off <<= 1) {
        int v = (t >= off) ? ssum[t - off] : 0;
        __syncthreads();
        ssum[t] += v;
        __syncthreads();
    }
    int pre = (t > 0) ? ssum[t - 1] : 0;
#pragma unroll
    for (int i = 0; i < 5; i++) {
        int idx = t * 5 + i;
        if (idx <= natoms) g_offsets[idx] = pre + loc[i];
    }
}
__global__ void rank_kernel(const int* __restrict__ centers, int np) {
    int p = blockIdx.x * blockDim.x + threadIdx.x;
    if (p < np) {
        int c = centers[p];
        int r = atomicAdd(&g_cursor[c], 1);
        g_sorted[g_offsets[c] + r] = p;
    }
}

// merged edge-weight build ---------------------------------------------------
#define PPB 16
__global__ void __launch_bounds__(128) wcomp_kernel(
    const float* __restrict__ sh, const float* __restrict__ rb, int np) {
    __shared__ float s_cg[NCG];
    __shared__ unsigned short s_ent[NCG];
    __shared__ int s_jse[256];
    __shared__ float s_edge[4][16];
    int tid = threadIdx.x;
    for (int i = tid; i < NCG; i += 128) { s_cg[i] = g_blob.cg[i]; s_ent[i] = g_blob.ent[i]; }
    for (int i = tid; i < 256; i += 128) s_jse[i] = g_blob.jse[i];
    __syncthreads();
    int warp = tid >> 5, lane = tid & 31;
#pragma unroll
    for (int pi = 0; pi < PPB / 4; pi++) {
        int p = blockIdx.x * PPB + warp + pi * 4;
        if (p >= np) break;
        if (lane < 16) {
            int l = (lane >= 9) ? 3 : (lane >= 4) ? 2 : (lane >= 1) ? 1 : 0;
            int rboff = (l == 3) ? 18 : (l == 2) ? 14 : (l == 1) ? 8 : 0;
            int rbsz = 8 - 2 * l;
            float rs = 0.f;
            for (int n = 0; n < rbsz; n++) rs += rb[(size_t)p * 20 + rboff + n];
            s_edge[warp][lane] = 0.1f * sh[(size_t)p * 16 + lane] * rs;
        }
        __syncwarp();
        float* wp = g_wall + (size_t)p * 256;
#pragma unroll
        for (int ii = 0; ii < 8; ii++) {
            int j = lane + 32 * ii;
            int se = s_jse[j];
            int st = se >> 16, cnt = se & 0xffff;
            float s = 0.f;
            for (int e = 0; e < cnt; e++) {
                unsigned en = s_ent[st + e];
                s += s_edge[warp][en >> 12] * s_cg[en & 0xfff];
            }
            wp[j] = s;
        }
        __syncwarp();
    }
}

// invariant MP ----------------------------------------------------------------
__global__ void __launch_bounds__(128) inv_kernel(
    const float* __restrict__ sh, const float* __restrict__ rb,
    const int* __restrict__ neighbors, float* __restrict__ bufA, int natoms) {
    __shared__ float s_in[2][68];
    int c = blockIdx.x;
    int tid = threadIdx.x, warp = tid >> 5, lane = tid & 31;
    int offj[15], shi[15], rbi[15];
#pragma unroll
    for (int ii = 0; ii < 15; ii++) {
        int j = warp + 4 * ii;
        offj[ii] = g_blob.inv_off[j];
        shi[ii]  = g_blob.inv_sh[j];
        rbi[ii]  = g_blob.inv_rb[j];
    }
    float acc[15];
#pragma unroll
    for (int ii = 0; ii < 15; ii++) acc[ii] = 0.f;

    int beg = g_offsets[c], end = g_offsets[c + 1];
    if (beg < end) {
        int p0 = g_sorted[beg];
        if (tid < 16)      s_in[0][tid] = sh[(size_t)p0 * 16 + tid];
        else if (tid < 36) s_in[0][tid] = rb[(size_t)p0 * 20 + (tid - 16)];
        else if (tid < 68) s_in[0][tid] = g_cemb[neighbors[p0] * 32 + (tid - 36)];
    }
    __syncthreads();
    for (int i = beg; i < end; i++) {
        int cur = (i - beg) & 1;
        float nst = 0.f;
        bool more = (i + 1 < end);
        if (more && tid < 68) {
            int pn = g_sorted[i + 1];
            if (tid < 16)      nst = sh[(size_t)pn * 16 + tid];
            else if (tid < 36) nst = rb[(size_t)pn * 20 + (tid - 16)];
            else               nst = g_cemb[neighbors[pn] * 32 + (tid - 36)];
        }
        float e = s_in[cur][36 + lane];
#pragma unroll
        for (int ii = 0; ii < 15; ii++)
            acc[ii] += s_in[cur][shi[ii]] * s_in[cur][16 + rbi[ii]] * e;
        if (more && tid < 68) s_in[cur ^ 1][tid] = nst;
        __syncthreads();
    }
    float* fb = bufA + (size_t)c * FSTRIDE;
#pragma unroll
    for (int ii = 0; ii < 15; ii++) fb[offj[ii] + lane] = 0.01f * acc[ii];
}

// ---------------------------------------------------------------------------
// TP with immediate coefficients: feat += 0.1*TP(feat,feat), no smem at all.
// ---------------------------------------------------------------------------
template <int LV>
__device__ __forceinline__ void tp_body(float* __restrict__ fb, int k) {
    constexpr int MM = (LV + 1) * (LV + 1);
    float A0[MM], A1[MM], c0[MM], c1[MM];
#pragma unroll
    for (int l = 0; l <= LV; l++)
#pragma unroll
        for (int m = 0; m < 2 * l + 1; m++) {
            float2 v = *reinterpret_cast<const float2*>(&fb[FOFFf(l) + m * KLf(l) + k]);
            A0[l * l + m] = v.x;
            A1[l * l + m] = v.y;
        }
#pragma unroll
    for (int i = 0; i < MM; i++) { c0[i] = 0.f; c1[i] = 0.f; }

    float p0 = 0.f, p1 = 0.f;
    tp_run<LV, 0, TL_t<LV>::v.n, MM>(A0, A1, c0, c1, p0, p1);

#pragma unroll
    for (int l = 0; l <= LV; l++)
#pragma unroll
        for (int m = 0; m < 2 * l + 1; m++) {
            int i = l * l + m;
            float2 v;
            v.x = fmaf(0.1f, c0[i], A0[i]);
            v.y = fmaf(0.1f, c1[i], A1[i]);
            *reinterpret_cast<float2*>(&fb[FOFFf(l) + m * KLf(l) + k]) = v;
        }
}

__global__ void __launch_bounds__(512) tp_fused_kernel(float* __restrict__ buf, int natoms) {
    int warp = threadIdx.x >> 5, lane = threadIdx.x & 31;
    int atomI = blockIdx.x * 4 + (warp >> 2);
    if (atomI >= natoms) return;
    int bk = ((warp & 3) + atomI) & 3;   // band; LV = 3 - bk
    int k = bk * 64 + lane * 2;
    float* fb = buf + (size_t)atomI * FSTRIDE;
    if (bk == 0)      tp_body<3>(fb, k);
    else if (bk == 1) tp_body<2>(fb, k);
    else if (bk == 2) tp_body<1>(fb, k);
    else              tp_body<0>(fb, k);
}

// ---------------------------------------------------------------------------
// equivariant MP — byte-identical to the 917 µs R8 version
// ---------------------------------------------------------------------------
template <int LV>
__device__ __forceinline__ void eq_acc2(const float* __restrict__ fan, ull ce2,
                                        const float* __restrict__ sw2, int k, ull* acc) {
    ull f[(LV + 1) * (LV + 1)];
#pragma unroll
    for (int l = 0; l <= LV; l++)
#pragma unroll
        for (int b = 0; b < 2 * l + 1; b++) {
            ull v = *reinterpret_cast<const ull*>(&fan[FOFFf(l) + b * KLf(l) + k]);
            f[l * l + b] = f2_mul(v, ce2);
        }
#pragma unroll
    for (int l2 = 0; l2 <= LV; l2++)
#pragma unroll
        for (int b = 0; b < 2 * l2 + 1; b++) {
            ull fb = f[l2 * l2 + b];
            const int lm2 = l2 * l2 + b;
#pragma unroll
            for (int L = 0; L <= LV; L++)
#pragma unroll
                for (int M = 0; M < 2 * L + 1; M++) {
                    ull w2 = *reinterpret_cast<const ull*>(&sw2[2 * (lm2 * 16 + L * L + M)]);
                    acc[L * L + M] = f2_fma(w2, fb, acc[L * L + M]);
                }
        }
}

template <int LV>
__device__ __forceinline__ void eq_write2(float* __restrict__ mpb, int k, const ull* acc) {
    ull sc = f2_dup(0.1f);
#pragma unroll
    for (int L = 0; L <= LV; L++)
#pragma unroll
        for (int M = 0; M < 2 * L + 1; M++) {
            ull v = f2_mul(sc, acc[L * L + M]);
            *reinterpret_cast<ull*>(&mpb[FOFFf(L) + M * KLf(L) + k]) = v;
        }
}

__global__ void __launch_bounds__(128) eq_kernel(
    const int* __restrict__ neighbors,
    const float* __restrict__ bufA, float* __restrict__ bufB, int natoms) {
    __shared__ __align__(16) float s_w2[2][512];
    int c = blockIdx.x;
    int tid = threadIdx.x, warp = tid >> 5, lane = tid & 31;
    int bk = (warp + c) & 3;
    int k = bk * 64 + lane * 2;
    ull acc[16];
#pragma unroll
    for (int i = 0; i < 16; i++) acc[i] = 0ull;

    int beg = g_offsets[c], end = g_offsets[c + 1];
    int nbr_cur = 0;
    if (beg < end) {
        int p0 = g_sorted[beg];
        nbr_cur = neighbors[p0];
        const float* wp = g_wall + (size_t)p0 * 256;
#pragma unroll
        for (int jj = 0; jj < 2; jj++) {
            int j = tid + jj * 128;
            float v = wp[j];
            *reinterpret_cast<float2*>(&s_w2[0][2 * j]) = make_float2(v, v);
        }
    }
    __syncthreads();
    for (int i = beg; i < end; i++) {
        int cur = (i - beg) & 1;
        bool more = (i + 1 < end);
        float nst0 = 0.f, nst1 = 0.f;
        int nbr_next = 0;
        if (more) {
            int pn = g_sorted[i + 1];
            nbr_next = neighbors[pn];
            const float* wp = g_wall + (size_t)pn * 256;
            nst0 = wp[tid];
            nst1 = wp[tid + 128];
        }
        const float* fan = bufA + (size_t)nbr_cur * FSTRIDE;
        float2 cef = *reinterpret_cast<const float2*>(&g_cemb[nbr_cur * 32 + 2 * (lane & 15)]);
        ull ce2 = *reinterpret_cast<ull*>(&cef);
        const float* sw = s_w2[cur];
        if (bk == 0)      eq_acc2<3>(fan, ce2, sw, k, acc);
        else if (bk == 1) eq_acc2<2>(fan, ce2, sw, k, acc);
        else if (bk == 2) eq_acc2<1>(fan, ce2, sw, k, acc);
        else              eq_acc2<0>(fan, ce2, sw, k, acc);
        if (more) {
            *reinterpret_cast<float2*>(&s_w2[cur ^ 1][2 * tid]) = make_float2(nst0, nst0);
            *reinterpret_cast<float2*>(&s_w2[cur ^ 1][2 * (tid + 128)]) = make_float2(nst1, nst1);
            nbr_cur = nbr_next;
        }
        __syncthreads();
    }
    float* mpb = bufB + (size_t)c * FSTRIDE;
    if (bk == 0)      eq_write2<3>(mpb, k, acc);
    else if (bk == 1) eq_write2<2>(mpb, k, acc);
    else if (bk == 2) eq_write2<1>(mpb, k, acc);
    else              eq_write2<0>(mpb, k, acc);
}

// energy ----------------------------------------------------------------------
__global__ void energy_kernel(const float* __restrict__ buf,
                              const float* __restrict__ we, const float* __restrict__ be,
                              float* __restrict__ out, int natoms) {
    int atomI = blockIdx.x * 4 + (threadIdx.x >> 5);
    int lane = threadIdx.x & 31;
    if (atomI >= natoms) return;
    float e = g_cemb[atomI * 32 + lane];
    const float* fb = buf + (size_t)atomI * FSTRIDE;
    float s = 0.f;
#pragma unroll
    for (int kk = 0; kk < 8; kk++) s += fb[kk * 32 + lane] * we[kk * 32 + lane];
    s *= e;
#pragma unroll
    for (int o = 16; o > 0; o >>= 1) s += __shfl_xor_sync(0xffffffffu, s, o);
    if (lane == 0) out[atomI] = s + be[0];
}

// ---------------------------------------------------------------------------
// host: runtime MT for the wcomp cg table (proven path) + wcomp/inv tables
// ---------------------------------------------------------------------------
static uint32_t s_mt[624];
static int s_mti;
static uint32_t mt_next() {
    if (s_mti >= 624) {
        for (int kk = 0; kk < 624; kk++) {
            uint32_t y = (s_mt[kk] & 0x80000000u) | (s_mt[(kk + 1) % 624] & 0x7fffffffu);
            s_mt[kk] = s_mt[(kk + 397) % 624] ^ (y >> 1) ^ ((y & 1u) ? 2567483615u : 0u);
        }
        s_mti = 0;
    }
    uint32_t y = s_mt[s_mti++];
    y ^= y >> 11;
    y ^= (y << 7) & 2636928640u;
    y ^= (y << 15) & 4022730752u;
    y ^= y >> 18;
    return y;
}
static double mt_double() {
    uint32_t a = mt_next() >> 5, b = mt_next() >> 6;
    return (a * 67108864.0 + b) / 9007199254740992.0;
}

static void build_blob(Blob& B) {
    uint32_t seed = 0;
    for (int pos = 0; pos < 624; pos++) {
        s_mt[pos] = seed;
        seed = 1812433253u * (seed ^ (seed >> 30)) + (uint32_t)pos + 1u;
    }
    s_mti = 624;
    int has_g = 0;
    double gcache = 0.0;
    for (int t = 0; t < NCG; t++) {
        double g;
        if (has_g) { g = gcache; has_g = 0; }
        else {
            double x1, x2, r2, f;
            do {
                x1 = 2.0 * mt_double() - 1.0;
                x2 = 2.0 * mt_double() - 1.0;
                r2 = x1 * x1 + x2 * x2;
            } while (r2 >= 1.0 || r2 == 0.0);
            f = sqrt(-2.0 * log(r2) / r2);
            gcache = f * x1;
            has_g = 1;
            g = f * x2;
        }
        B.cg[t] = (float)(g * 0.2);
    }
    static unsigned short tmp[256][16];
    static int cnt[256];
    memset(cnt, 0, sizeof(cnt));
    for (int tt = 0; tt < NT; tt++) {
        int l1 = CT_L1[tt], l2 = CT_L2[tt], L = CT_LL[tt];
        for (int a = 0; a < 2 * l1 + 1; a++)
            for (int b = 0; b < 2 * l2 + 1; b++)
                for (int M = 0; M < 2 * L + 1; M++) {
                    int j = (l2 * l2 + b) * 16 + L * L + M;
                    int cg_off = CT_CG[tt] + (a * (2 * l2 + 1) + b) * (2 * L + 1) + M;
                    tmp[j][cnt[j]++] = (unsigned short)(((l1 * l1 + a) << 12) | cg_off);
                }
    }
    int pos = 0;
    for (int j = 0; j < 256; j++) {
        B.jse[j] = (pos << 16) | cnt[j];
        for (int e = 0; e < cnt[j]; e++) B.ent[pos++] = tmp[j][e];
    }
    int j2 = 0;
    for (int l = 0; l < 4; l++)
        for (int m = 0; m < 2 * l + 1; m++)
            for (int n = 0; n < H_NMAX[l]; n++) {
                B.inv_off[j2] = FOFFf(l) + m * KLf(l) + n * 32;
                B.inv_sh[j2]  = l * l + m;
                B.inv_rb[j2]  = H_RBOFF[l] + n;
                j2++;
            }
}

static Blob h_blob;   // static: must outlive graph replays (memcpy node source)

// ---------------------------------------------------------------------------
extern "C" void kernel_launch(void* const* d_in, const int* in_sizes, int n_in,
                              void* d_out, int out_size) {
    const float* sh        = (const float*)d_in[0];
    const float* rb        = (const float*)d_in[1];
    const float* emb_table = (const float*)d_in[2];
    const float* w_energy  = (const float*)d_in[3];
    const float* b_energy  = (const float*)d_in[4];
    const int*   species   = (const int*)d_in[5];
    const int*   centers   = (const int*)d_in[6];
    const int*   neighbors = (const int*)d_in[7];
    int natoms = in_sizes[5];
    int np     = in_sizes[6];
    if (natoms > NATOM_MAX) natoms = NATOM_MAX;
    if (np > NPAIR_MAX)     np = NPAIR_MAX;
    float* out = (float*)d_out;

    build_blob(h_blob);
    cudaMemcpyToSymbolAsync(g_blob, &h_blob, sizeof(Blob), 0, cudaMemcpyHostToDevice, 0);

    float *bufA = nullptr, *bufB = nullptr;
    cudaGetSymbolAddress((void**)&bufA, g_bufA);
    cudaGetSymbolAddress((void**)&bufB, g_bufB);

    // embeddings + counting sort of pairs by center
    cemb_kernel<<<(natoms * 32 + 255) / 256, 256>>>(emb_table, species, natoms);
    zero_kernel<<<(natoms + 255) / 256, 256>>>(natoms);
    hist_kernel<<<(np + 255) / 256, 256>>>(centers, np);
    scan_kernel<<<1, 1024>>>(natoms);
    rank_kernel<<<(np + 255) / 256, 256>>>(centers, np);

    // merged per-pair edge-weight matrices (dense 16x16)
    wcomp_kernel<<<(np + PPB - 1) / PPB, 128>>>(sh, rb, np);

    // invariant MP (gather) -> bufA
    inv_kernel<<<natoms, 128>>>(sh, rb, neighbors, bufA, natoms);

    // cg_iterate #1 (symmetrized TP, immediate coefficients)
    tp_fused_kernel<<<(natoms + 3) / 4, 512>>>(bufA, natoms);

    // equivariant MP: reads bufA (embed folded) + g_wall, writes bufB
    eq_kernel<<<natoms, 128>>>(neighbors, bufA, bufB, natoms);

    // cg_iterate #2
    tp_fused_kernel<<<(natoms + 3) / 4, 512>>>(bufB, natoms);

    // final embed folded into energy readout
    energy_kernel<<<(natoms + 3) / 4, 128>>>(bufB, w_energy, b_energy, out, natoms);
}